// round 5
// baseline (speedup 1.0000x reference)
#include <cuda_runtime.h>
#include <cuda_bf16.h>
#include <math.h>
#include <stdint.h>

// Problem constants (reference: G=2048, CROPS=4, D=128 -> N=8192)
#define N_ROWS 8192
#define DIM    128
#define NP     (N_ROWS / 128)            // 64 row panels
#define CHUNK  4                         // J-tiles per CTA (sync-free strip)

#define EXP2_SCALE 2.8853900817779268f   // 1/(tau*ln2), tau=0.5
#define SQRT_E2S   1.6986436f            // sqrt(EXP2_SCALE), folded into bf16 z
#define EXP_SELF   7.38905609893065f     // exp(1/tau) = e^2

// Scratch (device globals; no allocation anywhere)
__device__ float          g_z[N_ROWS * DIM];        // fp32 normalized (unscaled)
__device__ __nv_bfloat16  g_zb[N_ROWS * DIM];       // bf16 normalized * sqrt(scale)
__device__ float          g_P[NP * NP * 128];       // per-(panel,slot) partial sums
__device__ float          g_part[N_ROWS / 8];       // per-CTA partial losses
__device__ int            g_sync;                   // last-CTA counter (self-resetting)

// ---------------------------------------------------------------------------
// helpers
// ---------------------------------------------------------------------------
static __device__ __forceinline__ uint32_t smem_u32(const void* p) {
    uint32_t a;
    asm("{ .reg .u64 t; cvta.to.shared.u64 t, %1; cvt.u32.u64 %0, t; }"
        : "=r"(a) : "l"(p));
    return a;
}

#define LDSM_X4(r0, r1, r2, r3, addr)                                          \
    asm volatile("ldmatrix.sync.aligned.m8n8.x4.shared.b16 {%0,%1,%2,%3}, [%4];" \
                 : "=r"(r0), "=r"(r1), "=r"(r2), "=r"(r3) : "r"(addr))

#define MMA16816(d, a, b0, b1)                                                 \
    asm volatile("mma.sync.aligned.m16n8k16.row.col.f32.bf16.bf16.f32 "        \
                 "{%0,%1,%2,%3},{%4,%5,%6,%7},{%8,%9},{%0,%1,%2,%3};"          \
                 : "+f"((d)[0]), "+f"((d)[1]), "+f"((d)[2]), "+f"((d)[3])      \
                 : "r"((a)[0]), "r"((a)[1]), "r"((a)[2]), "r"((a)[3]),         \
                   "r"(b0), "r"(b1))

#define CP_ASYNC16(dst, src)                                                   \
    asm volatile("cp.async.cg.shared.global [%0], [%1], 16;"                   \
                 :: "r"(dst), "l"(src) : "memory")
#define CP_COMMIT() asm volatile("cp.async.commit_group;" ::: "memory")
#define CP_WAIT(N)  asm volatile("cp.async.wait_group %0;" :: "n"(N) : "memory")

static __device__ __forceinline__ float ex2_fast(float x) {
    float y;
    asm("ex2.approx.ftz.f32 %0, %1;" : "=f"(y) : "f"(x));
    return y;
}

// Swizzled tile layout (128 rows x 16 chunks of 16B, conflict-free ldmatrix):
// off(r,c) = (c>>3)*16384 + r*128 + ((c&7)^(r&7))*16
static __device__ __forceinline__ uint32_t tile_off(int r, int c) {
    return ((uint32_t)(c >> 3) << 14) + ((uint32_t)r << 7)
         + ((uint32_t)((c & 7) ^ (r & 7)) << 4);
}

// async-copy one 128x128 bf16 panel (rows r0..r0+127) into swizzled smem
static __device__ __forceinline__ void cp_tile(uint32_t dst, int r0, int tid) {
    const char* src = (const char*)g_zb + (size_t)r0 * 256;
    #pragma unroll
    for (int it = 0; it < 8; it++) {
        int idx = tid + it * 256;       // 2048 chunks of 16B
        int r = idx >> 4;
        int c = idx & 15;
        CP_ASYNC16(dst + tile_off(r, c), src + (size_t)r * 256 + c * 16);
    }
}

// ---------------------------------------------------------------------------
// Kernel A: row-normalize; fp32 copy + bf16 copy pre-scaled by sqrt(EXP2_SCALE)
// ---------------------------------------------------------------------------
__global__ void k_normalize(const float* __restrict__ f, int n) {
    int warp = (blockIdx.x * blockDim.x + threadIdx.x) >> 5;
    int lane = threadIdx.x & 31;
    if (warp >= n) return;
    const float* row = f + (size_t)warp * DIM;
    float v0 = row[lane], v1 = row[lane + 32], v2 = row[lane + 64], v3 = row[lane + 96];
    float ss = v0 * v0 + v1 * v1 + v2 * v2 + v3 * v3;
    #pragma unroll
    for (int o = 16; o; o >>= 1) ss += __shfl_xor_sync(0xffffffffu, ss, o);
    float inv = 1.0f / fmaxf(sqrtf(ss), 1e-8f);
    float z0 = v0 * inv, z1 = v1 * inv, z2 = v2 * inv, z3 = v3 * inv;
    float* z = g_z + (size_t)warp * DIM;
    z[lane] = z0; z[lane + 32] = z1; z[lane + 64] = z2; z[lane + 96] = z3;
    __nv_bfloat16* zb = g_zb + (size_t)warp * DIM;
    zb[lane]      = __float2bfloat16(z0 * SQRT_E2S);
    zb[lane + 32] = __float2bfloat16(z1 * SQRT_E2S);
    zb[lane + 64] = __float2bfloat16(z2 * SQRT_E2S);
    zb[lane + 96] = __float2bfloat16(z3 * SQRT_E2S);
}

// ---------------------------------------------------------------------------
// Kernel B: symmetric-strip HMMA. grid (NP, 16): CTA = tiles (I, J0..J0+nt-1),
// J0 = I + 4*blockIdx.y. Sync-free mainloop: A + nt B panels preloaded; warps
// slip phase across tiles so tensor (MMA) and MUFU (ex2) pipes overlap.
// Per-tile private smem reduction slots; single final sync + gather.
// ---------------------------------------------------------------------------
__global__ void __launch_bounds__(256, 1)
k_scores_sym() {
    const int I  = blockIdx.x;
    const int J0 = I + blockIdx.y * CHUNK;
    if (J0 >= NP) return;
    const int nt = (NP - J0 < CHUNK) ? (NP - J0) : CHUNK;

    extern __shared__ __align__(1024) char smem[];
    __shared__ float red[CHUNK][128][2];      // row sums:  [tile][row][warpN]
    __shared__ float colred[CHUNK][128][4];   // col sums:  [tile][col][warpM]

    const uint32_t Abase = smem_u32(smem);

    const int tid   = threadIdx.x;
    const int lane  = tid & 31;
    const int w     = tid >> 5;
    const int warpM = w & 3;
    const int warpN = w >> 2;

    // Prologue: load A panel + nt B panels, one wait, one sync.
    cp_tile(Abase, I * 128, tid);
    for (int t = 0; t < nt; t++)
        cp_tile(Abase + (1 + t) * 32768, (J0 + t) * 128, tid);
    CP_COMMIT();
    CP_WAIT(0);
    __syncthreads();

    // A fragments live in registers across all tiles
    const int aRow = warpM * 32 + (lane & 15);
    const int aSel = lane >> 4;
    uint32_t afrag[2][8][4];
    #pragma unroll
    for (int mb = 0; mb < 2; mb++)
        #pragma unroll
        for (int ks = 0; ks < 8; ks++)
            LDSM_X4(afrag[mb][ks][0], afrag[mb][ks][1],
                    afrag[mb][ks][2], afrag[mb][ks][3],
                    Abase + tile_off(aRow + mb * 16, ks * 2 + aSel));

    const int bRow = (lane & 7) + ((lane >> 4) & 1) * 8;
    const int bSel = (lane >> 3) & 1;

    for (int tt = 0; tt < nt; tt++) {
        const uint32_t Bb = Abase + (uint32_t)(1 + tt) * 32768u;

        float acc[2][8][4];
        #pragma unroll
        for (int mb = 0; mb < 2; mb++)
            #pragma unroll
            for (int nb = 0; nb < 8; nb++)
                #pragma unroll
                for (int q = 0; q < 4; q++) acc[mb][nb][q] = 0.0f;

        #pragma unroll
        for (int ks = 0; ks < 8; ks++) {
            #pragma unroll
            for (int nb2 = 0; nb2 < 4; nb2++) {
                uint32_t b0, b1, b2, b3;
                LDSM_X4(b0, b1, b2, b3,
                        Bb + tile_off(warpN * 64 + nb2 * 16 + bRow, ks * 2 + bSel));
                #pragma unroll
                for (int mb = 0; mb < 2; mb++) {
                    MMA16816(acc[mb][nb2 * 2],     afrag[mb][ks], b0, b1);
                    MMA16816(acc[mb][nb2 * 2 + 1], afrag[mb][ks], b2, b3);
                }
            }
        }

        // Epilogue: exp2 (operands pre-scaled); row + col partial sums
        float rs[2][2] = {{0.f, 0.f}, {0.f, 0.f}};
        float cs[16];
        #pragma unroll
        for (int k = 0; k < 16; k++) cs[k] = 0.f;

        #pragma unroll
        for (int mb = 0; mb < 2; mb++)
            #pragma unroll
            for (int nb = 0; nb < 8; nb++)
                #pragma unroll
                for (int q = 0; q < 4; q++) {
                    float e = ex2_fast(acc[mb][nb][q]);
                    rs[mb][q >> 1]       += e;
                    cs[nb * 2 + (q & 1)] += e;
                }

        #pragma unroll
        for (int mb = 0; mb < 2; mb++)
            #pragma unroll
            for (int h = 0; h < 2; h++) {
                rs[mb][h] += __shfl_xor_sync(0xffffffffu, rs[mb][h], 1);
                rs[mb][h] += __shfl_xor_sync(0xffffffffu, rs[mb][h], 2);
            }
        #pragma unroll
        for (int k = 0; k < 16; k++) {
            cs[k] += __shfl_xor_sync(0xffffffffu, cs[k], 4);
            cs[k] += __shfl_xor_sync(0xffffffffu, cs[k], 8);
            cs[k] += __shfl_xor_sync(0xffffffffu, cs[k], 16);
        }

        if ((lane & 3) == 0) {
            int gq = lane >> 2;
            #pragma unroll
            for (int mb = 0; mb < 2; mb++)
                #pragma unroll
                for (int h = 0; h < 2; h++)
                    red[tt][warpM * 32 + mb * 16 + h * 8 + gq][warpN] = rs[mb][h];
        }
        if (lane < 4) {
            #pragma unroll
            for (int k = 0; k < 16; k++)
                colred[tt][warpN * 64 + (k >> 1) * 8 + lane * 2 + (k & 1)][warpM] = cs[k];
        }
        // no __syncthreads: per-tile private slots; warps slip freely
    }

    __syncthreads();   // all tiles' reduction slots complete

    if (tid < 128) {
        for (int tt = 0; tt < nt; tt++) {
            const int J = J0 + tt;
            float r = red[tt][tid][0] + red[tt][tid][1];
            g_P[((size_t)I * NP + J) * 128 + tid] = r;
            if (J != I) {
                float c = colred[tt][tid][0] + colred[tt][tid][1]
                        + colred[tt][tid][2] + colred[tt][tid][3];
                g_P[((size_t)J * NP + I) * 128 + tid] = c;
            }
        }
    }
}

// ---------------------------------------------------------------------------
// Kernel C: gather S + fp32 pos + per-row loss + CTA partials + fused final
// reduction (deterministic last-CTA pattern; counter self-resets per replay)
// ---------------------------------------------------------------------------
__global__ void k_rowloss(float* __restrict__ out, int n, int cr) {
    __shared__ float tvals[8];
    __shared__ int   s_last;
    __shared__ float sm[256];

    int row  = blockIdx.x * 8 + (threadIdx.x >> 5);
    int lane = threadIdx.x & 31;
    float tv = 0.0f;
    if (row < n) {
        const float* zr = g_z + (size_t)row * DIM;
        float a0 = zr[lane], a1 = zr[lane + 32], a2 = zr[lane + 64], a3 = zr[lane + 96];
        int gb = (row / cr) * cr;
        float P = 0.0f;
        for (int jj = 0; jj < cr; jj++) {
            const float* zc = g_z + (size_t)(gb + jj) * DIM;
            float d = a0 * zc[lane] + a1 * zc[lane + 32] + a2 * zc[lane + 64] + a3 * zc[lane + 96];
            #pragma unroll
            for (int o = 16; o; o >>= 1) d += __shfl_xor_sync(0xffffffffu, d, o);
            P += exp2f(d * EXP2_SCALE);
        }
        int Ip   = row >> 7;
        int r127 = row & 127;
        const float* pbase = g_P + (size_t)Ip * NP * 128 + r127;
        float s = pbase[(size_t)lane * 128] + pbase[(size_t)(lane + 32) * 128];
        #pragma unroll
        for (int o = 16; o; o >>= 1) s += __shfl_xor_sync(0xffffffffu, s, o);

        float pos = P - EXP_SELF;
        float neg = s - P;
        tv = logf(neg) - logf(pos);
    }
    if (lane == 0) tvals[threadIdx.x >> 5] = tv;
    __syncthreads();
    if (threadIdx.x == 0) {
        float acc = 0.0f;
        #pragma unroll
        for (int u = 0; u < 8; u++) acc += tvals[u];
        g_part[blockIdx.x] = acc;
        __threadfence();
        int old = atomicAdd(&g_sync, 1);
        s_last = (old == (int)gridDim.x - 1);
    }
    __syncthreads();

    if (s_last) {
        if (threadIdx.x == 0) g_sync = 0;   // reset for next graph replay
        __threadfence();
        int t = threadIdx.x;
        int m = gridDim.x;
        float s = 0.0f;
        for (int idx = t; idx < m; idx += 256)
            s += __ldcg(&g_part[idx]);      // fixed-order, L2 loads
        sm[t] = s;
        __syncthreads();
        #pragma unroll
        for (int off = 128; off; off >>= 1) {
            if (t < off) sm[t] += sm[t + off];
            __syncthreads();
        }
        if (t == 0) out[0] = sm[0] / (float)n;
    }
}

// ---------------------------------------------------------------------------
extern "C" void kernel_launch(void* const* d_in, const int* in_sizes, int n_in,
                              void* d_out, int out_size) {
    const float* features = (const float*)d_in[0];
    int n  = in_sizes[0] / DIM;   // 8192
    int g  = in_sizes[1];         // 2048
    int cr = n / g;               // 4

    const int SMEM_DYN = (1 + CHUNK) * 32768;   // A + 4 B panels = 160KB
    cudaFuncSetAttribute(k_scores_sym,
                         cudaFuncAttributeMaxDynamicSharedMemorySize, SMEM_DYN);

    k_normalize<<<n / 8, 256>>>(features, n);
    dim3 grid_b(NP, (NP + CHUNK - 1) / CHUNK);
    k_scores_sym<<<grid_b, 256, SMEM_DYN>>>();
    k_rowloss<<<n / 8, 256>>>((float*)d_out, n, cr);
}

// round 6
// speedup vs baseline: 1.1558x; 1.1558x over previous
#include <cuda_runtime.h>
#include <cuda_bf16.h>
#include <math.h>
#include <stdint.h>

// Problem constants (reference: G=2048, CROPS=4, D=128 -> N=8192)
#define N_ROWS 8192
#define DIM    128
#define NP     (N_ROWS / 128)            // 64 row panels

#define EXP2_SCALE 2.8853900817779268f   // 1/(tau*ln2), tau=0.5
#define SQRT_E2S   1.6986436f            // sqrt(EXP2_SCALE), folded into bf16 z
#define EXP_SELF   7.38905609893065f     // exp(1/tau) = e^2

// Scratch (device globals; no allocation anywhere)
__device__ float          g_z[N_ROWS * DIM];        // fp32 normalized (unscaled)
__device__ __nv_bfloat16  g_zb[N_ROWS * DIM];       // bf16 normalized * sqrt(scale)
__device__ float          g_P[NP * NP * 128];       // per-(panel,slot) partial sums
__device__ float          g_part[N_ROWS / 8];       // per-CTA partial losses
__device__ int            g_sync;                   // last-CTA counter (self-resetting)

// ---------------------------------------------------------------------------
// helpers
// ---------------------------------------------------------------------------
static __device__ __forceinline__ uint32_t smem_u32(const void* p) {
    uint32_t a;
    asm("{ .reg .u64 t; cvta.to.shared.u64 t, %1; cvt.u32.u64 %0, t; }"
        : "=r"(a) : "l"(p));
    return a;
}

#define LDSM_X4(r0, r1, r2, r3, addr)                                          \
    asm volatile("ldmatrix.sync.aligned.m8n8.x4.shared.b16 {%0,%1,%2,%3}, [%4];" \
                 : "=r"(r0), "=r"(r1), "=r"(r2), "=r"(r3) : "r"(addr))

#define MMA16816(d, a, b0, b1)                                                 \
    asm volatile("mma.sync.aligned.m16n8k16.row.col.f32.bf16.bf16.f32 "        \
                 "{%0,%1,%2,%3},{%4,%5,%6,%7},{%8,%9},{%0,%1,%2,%3};"          \
                 : "+f"((d)[0]), "+f"((d)[1]), "+f"((d)[2]), "+f"((d)[3])      \
                 : "r"((a)[0]), "r"((a)[1]), "r"((a)[2]), "r"((a)[3]),         \
                   "r"(b0), "r"(b1))

#define CP_ASYNC16(dst, src)                                                   \
    asm volatile("cp.async.cg.shared.global [%0], [%1], 16;"                   \
                 :: "r"(dst), "l"(src) : "memory")
#define CP_COMMIT() asm volatile("cp.async.commit_group;" ::: "memory")
#define CP_WAIT(N)  asm volatile("cp.async.wait_group %0;" :: "n"(N) : "memory")

static __device__ __forceinline__ float ex2_fast(float x) {
    float y;
    asm("ex2.approx.ftz.f32 %0, %1;" : "=f"(y) : "f"(x));
    return y;
}

// Swizzled tile layout (128 rows x 16 chunks of 16B, conflict-free ldmatrix):
// off(r,c) = (c>>3)*16384 + r*128 + ((c&7)^(r&7))*16
static __device__ __forceinline__ uint32_t tile_off(int r, int c) {
    return ((uint32_t)(c >> 3) << 14) + ((uint32_t)r << 7)
         + ((uint32_t)((c & 7) ^ (r & 7)) << 4);
}

// async-copy one 128x128 bf16 panel (rows r0..r0+127) into swizzled smem
static __device__ __forceinline__ void cp_tile(uint32_t dst, int r0, int tid) {
    const char* src = (const char*)g_zb + (size_t)r0 * 256;
    #pragma unroll
    for (int it = 0; it < 8; it++) {
        int idx = tid + it * 256;       // 2048 chunks of 16B
        int r = idx >> 4;
        int c = idx & 15;
        CP_ASYNC16(dst + tile_off(r, c), src + (size_t)r * 256 + c * 16);
    }
}

// ---------------------------------------------------------------------------
// Kernel A: row-normalize; fp32 copy + bf16 copy pre-scaled by sqrt(EXP2_SCALE)
// ---------------------------------------------------------------------------
__global__ void k_normalize(const float* __restrict__ f, int n) {
    int warp = (blockIdx.x * blockDim.x + threadIdx.x) >> 5;
    int lane = threadIdx.x & 31;
    if (warp >= n) return;
    const float* row = f + (size_t)warp * DIM;
    float v0 = row[lane], v1 = row[lane + 32], v2 = row[lane + 64], v3 = row[lane + 96];
    float ss = v0 * v0 + v1 * v1 + v2 * v2 + v3 * v3;
    #pragma unroll
    for (int o = 16; o; o >>= 1) ss += __shfl_xor_sync(0xffffffffu, ss, o);
    float inv = 1.0f / fmaxf(sqrtf(ss), 1e-8f);
    float z0 = v0 * inv, z1 = v1 * inv, z2 = v2 * inv, z3 = v3 * inv;
    float* z = g_z + (size_t)warp * DIM;
    z[lane] = z0; z[lane + 32] = z1; z[lane + 64] = z2; z[lane + 96] = z3;
    __nv_bfloat16* zb = g_zb + (size_t)warp * DIM;
    zb[lane]      = __float2bfloat16(z0 * SQRT_E2S);
    zb[lane + 32] = __float2bfloat16(z1 * SQRT_E2S);
    zb[lane + 64] = __float2bfloat16(z2 * SQRT_E2S);
    zb[lane + 96] = __float2bfloat16(z3 * SQRT_E2S);
}

// ---------------------------------------------------------------------------
// Kernel B: symmetric-tile HMMA, one 128x128 tile per CTA, occupancy 3.
// Mainloop restructured into 2 n-half-blocks: each block's k-reduction
// completes, then its ex2/FADD epilogue issues INTERLEAVED with the next
// block's MMAs (MUFU overlaps tensor within each warp).
// ---------------------------------------------------------------------------
__global__ void __launch_bounds__(256, 3)
k_scores_sym() {
    const int I = blockIdx.x;
    const int J = blockIdx.y;
    if (J < I) return;

    extern __shared__ __align__(1024) char smem[];
    __shared__ float red[128][2];      // row sums: [row][warpN]
    __shared__ float colred[128][4];   // col sums: [col][warpM]

    const uint32_t Abase = smem_u32(smem);
    const uint32_t Bbase = Abase + 32768;

    const int tid   = threadIdx.x;
    const int lane  = tid & 31;
    const int w     = tid >> 5;
    const int warpM = w & 3;
    const int warpN = w >> 2;

    cp_tile(Abase, I * 128, tid);
    cp_tile(Bbase, J * 128, tid);
    CP_COMMIT();
    CP_WAIT(0);
    __syncthreads();

    const int aRow = warpM * 32 + (lane & 15);
    const int aSel = lane >> 4;
    const int bRow = (lane & 7) + ((lane >> 4) & 1) * 8;
    const int bSel = (lane >> 3) & 1;

    float rs[2][2] = {{0.f, 0.f}, {0.f, 0.f}};

    #pragma unroll
    for (int nbb = 0; nbb < 2; nbb++) {       // n-half-block: cols nbb*32..+31
        float acc[2][2][2][4];                 // [mb][nb2loc][sub][q]
        #pragma unroll
        for (int mb = 0; mb < 2; mb++)
            #pragma unroll
            for (int u = 0; u < 2; u++)
                #pragma unroll
                for (int v = 0; v < 2; v++)
                    #pragma unroll
                    for (int q = 0; q < 4; q++) acc[mb][u][v][q] = 0.0f;

        #pragma unroll
        for (int ks = 0; ks < 8; ks++) {
            uint32_t af[2][4];
            #pragma unroll
            for (int mb = 0; mb < 2; mb++)
                LDSM_X4(af[mb][0], af[mb][1], af[mb][2], af[mb][3],
                        Abase + tile_off(aRow + mb * 16, ks * 2 + aSel));
            #pragma unroll
            for (int u = 0; u < 2; u++) {
                uint32_t b0, b1, b2, b3;
                LDSM_X4(b0, b1, b2, b3,
                        Bbase + tile_off(warpN * 64 + (nbb * 2 + u) * 16 + bRow,
                                         ks * 2 + bSel));
                #pragma unroll
                for (int mb = 0; mb < 2; mb++) {
                    MMA16816(acc[mb][u][0], af[mb], b0, b1);
                    MMA16816(acc[mb][u][1], af[mb], b2, b3);
                }
            }
        }

        // Block epilogue: ex2 + row/col partial sums (overlaps next block's MMAs)
        float cs[8];
        #pragma unroll
        for (int k = 0; k < 8; k++) cs[k] = 0.f;

        #pragma unroll
        for (int mb = 0; mb < 2; mb++)
            #pragma unroll
            for (int u = 0; u < 2; u++)
                #pragma unroll
                for (int v = 0; v < 2; v++)
                    #pragma unroll
                    for (int q = 0; q < 4; q++) {
                        float e = ex2_fast(acc[mb][u][v][q]);
                        rs[mb][q >> 1]            += e;
                        cs[(u * 2 + v) * 2 + (q & 1)] += e;
                    }

        // col reduce across lane>>2 (rows); lane<4 then holds col groups
        #pragma unroll
        for (int k = 0; k < 8; k++) {
            cs[k] += __shfl_xor_sync(0xffffffffu, cs[k], 4);
            cs[k] += __shfl_xor_sync(0xffffffffu, cs[k], 8);
            cs[k] += __shfl_xor_sync(0xffffffffu, cs[k], 16);
        }
        if (lane < 4) {
            #pragma unroll
            for (int k = 0; k < 8; k++) {
                int nb = nbb * 4 + (k >> 1);           // global 8-col group
                colred[warpN * 64 + nb * 8 + lane * 2 + (k & 1)][warpM] = cs[k];
            }
        }
    }

    // row reduce across lane&3 (cols)
    #pragma unroll
    for (int mb = 0; mb < 2; mb++)
        #pragma unroll
        for (int h = 0; h < 2; h++) {
            rs[mb][h] += __shfl_xor_sync(0xffffffffu, rs[mb][h], 1);
            rs[mb][h] += __shfl_xor_sync(0xffffffffu, rs[mb][h], 2);
        }
    if ((lane & 3) == 0) {
        int gq = lane >> 2;
        #pragma unroll
        for (int mb = 0; mb < 2; mb++)
            #pragma unroll
            for (int h = 0; h < 2; h++)
                red[warpM * 32 + mb * 16 + h * 8 + gq][warpN] = rs[mb][h];
    }
    __syncthreads();

    if (tid < 128) {
        float r = red[tid][0] + red[tid][1];
        g_P[((size_t)I * NP + J) * 128 + tid] = r;
        if (I != J) {
            float c = colred[tid][0] + colred[tid][1]
                    + colred[tid][2] + colred[tid][3];
            g_P[((size_t)J * NP + I) * 128 + tid] = c;
        }
    }
}

// ---------------------------------------------------------------------------
// Kernel C: gather S + fp32 pos + per-row loss + CTA partials + fused final
// reduction (deterministic last-CTA pattern; counter self-resets per replay)
// ---------------------------------------------------------------------------
__global__ void k_rowloss(float* __restrict__ out, int n, int cr) {
    __shared__ float tvals[8];
    __shared__ int   s_last;
    __shared__ float sm[256];

    int row  = blockIdx.x * 8 + (threadIdx.x >> 5);
    int lane = threadIdx.x & 31;
    float tv = 0.0f;
    if (row < n) {
        const float* zr = g_z + (size_t)row * DIM;
        float a0 = zr[lane], a1 = zr[lane + 32], a2 = zr[lane + 64], a3 = zr[lane + 96];
        int gb = (row / cr) * cr;
        float P = 0.0f;
        for (int jj = 0; jj < cr; jj++) {
            const float* zc = g_z + (size_t)(gb + jj) * DIM;
            float d = a0 * zc[lane] + a1 * zc[lane + 32] + a2 * zc[lane + 64] + a3 * zc[lane + 96];
            #pragma unroll
            for (int o = 16; o; o >>= 1) d += __shfl_xor_sync(0xffffffffu, d, o);
            P += exp2f(d * EXP2_SCALE);
        }
        int Ip   = row >> 7;
        int r127 = row & 127;
        const float* pbase = g_P + (size_t)Ip * NP * 128 + r127;
        float s = pbase[(size_t)lane * 128] + pbase[(size_t)(lane + 32) * 128];
        #pragma unroll
        for (int o = 16; o; o >>= 1) s += __shfl_xor_sync(0xffffffffu, s, o);

        float pos = P - EXP_SELF;
        float neg = s - P;
        tv = logf(neg) - logf(pos);
    }
    if (lane == 0) tvals[threadIdx.x >> 5] = tv;
    __syncthreads();
    if (threadIdx.x == 0) {
        float acc = 0.0f;
        #pragma unroll
        for (int u = 0; u < 8; u++) acc += tvals[u];
        g_part[blockIdx.x] = acc;
        __threadfence();
        int old = atomicAdd(&g_sync, 1);
        s_last = (old == (int)gridDim.x - 1);
    }
    __syncthreads();

    if (s_last) {
        if (threadIdx.x == 0) g_sync = 0;   // reset for next graph replay
        __threadfence();
        int t = threadIdx.x;
        int m = gridDim.x;
        float s = 0.0f;
        for (int idx = t; idx < m; idx += 256)
            s += __ldcg(&g_part[idx]);      // fixed-order, L2 loads
        sm[t] = s;
        __syncthreads();
        #pragma unroll
        for (int off = 128; off; off >>= 1) {
            if (t < off) sm[t] += sm[t + off];
            __syncthreads();
        }
        if (t == 0) out[0] = sm[0] / (float)n;
    }
}

// ---------------------------------------------------------------------------
extern "C" void kernel_launch(void* const* d_in, const int* in_sizes, int n_in,
                              void* d_out, int out_size) {
    const float* features = (const float*)d_in[0];
    int n  = in_sizes[0] / DIM;   // 8192
    int g  = in_sizes[1];         // 2048
    int cr = n / g;               // 4

    const int SMEM_DYN = 2 * 32768;   // A panel + B panel
    cudaFuncSetAttribute(k_scores_sym,
                         cudaFuncAttributeMaxDynamicSharedMemorySize, SMEM_DYN);

    k_normalize<<<n / 8, 256>>>(features, n);
    dim3 grid_b(NP, NP);
    k_scores_sym<<<grid_b, 256, SMEM_DYN>>>();
    k_rowloss<<<n / 8, 256>>>((float*)d_out, n, cr);
}